// round 5
// baseline (speedup 1.0000x reference)
#include <cuda_runtime.h>
#include <cstdint>
#include <cstddef>

#define Bb 16
#define Nn 307
#define NSTEP 11
#define Rr (Bb*Nn)   // 4912
#define AGK 320      // padded GEMM K / A stride
typedef unsigned long long ull;

// ---------------- device scratch (zero-initialized; pads never written) ----------------
__device__ float d_A[AGK*AGK];          // [320][320]; rows/cols >=307 stay 0
__device__ float d_agcW[(size_t)Nn*2*64*64];
__device__ float d_agcb[Nn*64];
__device__ float d_h[Rr*64];
__device__ float d_z[Rr*64];
__device__ float d_kh[Rr*64];
__device__ float d_kz[Rr*64];
__device__ float d_acch[Rr*64];
__device__ float d_accz[Rr*64];
__device__ float d_x1gT[(size_t)AGK*1024];  // [m][b*64+i]; rows >=307 stay 0
__device__ float d_yT[(size_t)Nn*1024];
__device__ float d_x2[Rr*64];

__device__ __forceinline__ float fast_tanh(float x){
    return 1.f - __fdividef(2.f, __expf(2.f*x) + 1.f);
}

// ---------------- fused precompute ----------------
#define PRE_AGCB_BLKS ((Nn*64 + 255)/256)
#define PRE_AGCW_BLKS ((Nn*8192 + 255)/256)
__global__ void k_pre(const float* __restrict__ gE,
                      const float* __restrict__ gbpool,
                      const float* __restrict__ gWpool){
    int tid = threadIdx.x;
    if (blockIdx.x < Nn){
        __shared__ float s[Nn];
        __shared__ float red[256];
        int n = blockIdx.x;
        float en[8];
        #pragma unroll
        for (int d=0; d<8; d++) en[d] = gE[n*8+d];
        for (int m=tid; m<Nn; m+=256){
            float acc = 0.f;
            #pragma unroll
            for (int d=0; d<8; d++) acc += en[d]*gE[m*8+d];
            s[m] = fmaxf(acc, 0.f);
        }
        __syncthreads();
        float mx = -1e30f;
        for (int m=tid; m<Nn; m+=256) mx = fmaxf(mx, s[m]);
        red[tid] = mx; __syncthreads();
        for (int o=128;o>0;o>>=1){ if (tid<o) red[tid]=fmaxf(red[tid],red[tid+o]); __syncthreads(); }
        mx = red[0]; __syncthreads();
        float sum = 0.f;
        for (int m=tid; m<Nn; m+=256){ float e = expf(s[m]-mx); s[m]=e; sum+=e; }
        red[tid]=sum; __syncthreads();
        for (int o=128;o>0;o>>=1){ if (tid<o) red[tid]+=red[tid+o]; __syncthreads(); }
        float inv = 1.f/red[0];
        for (int m=tid; m<Nn; m+=256) d_A[(size_t)n*AGK+m] = s[m]*inv;
    } else if (blockIdx.x < Nn + PRE_AGCB_BLKS){
        int idx = (blockIdx.x - Nn)*256 + tid;
        if (idx < Nn*64){
            int n = idx >> 6, o = idx & 63;
            float acc = 0.f;
            #pragma unroll
            for (int d=0; d<8; d++) acc += gE[n*8+d]*gbpool[d*64+o];
            d_agcb[idx] = acc;
        }
    } else {
        int idx = (blockIdx.x - Nn - PRE_AGCB_BLKS)*256 + tid;
        if (idx < Nn*8192){
            int n = idx >> 13;
            int rest = idx & 8191;
            float acc = 0.f;
            #pragma unroll
            for (int d=0; d<8; d++) acc += gE[n*8+d]*gWpool[(size_t)d*8192 + rest];
            d_agcW[idx] = acc;
        }
    }
}

// ---------------- per-stage kernels ----------------
__global__ void __launch_bounds__(64) k_fg1(
                      const float* __restrict__ times,
                      const float* __restrict__ coeff_a,
                      const float* __restrict__ cb, const float* __restrict__ cc, const float* __restrict__ cd,
                      const float* __restrict__ hW, const float* __restrict__ hb,
                      const float* __restrict__ zW, const float* __restrict__ zb,
                      const float* __restrict__ fWin, const float* __restrict__ fbin,
                      const float* __restrict__ fWmid, const float* __restrict__ fbmid,
                      const float* __restrict__ fWout, const float* __restrict__ fbout,
                      const float* __restrict__ gWin, const float* __restrict__ gbin,
                      int step, int stage){
    int t = threadIdx.x;
    int r0 = blockIdx.x * 8;
    __shared__ float sh[8*64], sz[8*64], sx[8*64];

    float t0 = times[step], t1 = times[step+1];
    float dt = t1 - t0;
    float c  = (stage==0) ? 0.f : ((stage==3) ? dt : 0.5f*dt);
    float tv = (stage==0) ? t0  : ((stage==3) ? t1 : (t0 + 0.5f*dt));
    float w  = (stage==1 || stage==2) ? 2.f : 1.f;

    if (stage == 0){
        if (step == 0){
            float wh0 = hW[t], wh1 = hW[64+t], bh = hb[t];
            float wz0 = zW[t], wz1 = zW[64+t], bz = zb[t];
            #pragma unroll
            for (int j=0;j<8;j++){
                int r = r0+j;
                float x0 = coeff_a[(size_t)r*(NSTEP*2) + 0];
                float x1 = coeff_a[(size_t)r*(NSTEP*2) + 1];
                float hv = x0*wh0 + x1*wh1 + bh;
                float zv = x0*wz0 + x1*wz1 + bz;
                size_t base = (size_t)r*64 + t;
                d_h[base] = hv; d_z[base] = zv;
                sh[j*64+t] = hv; sz[j*64+t] = zv;
            }
        } else {
            float scp = (times[step] - times[step-1]) * (1.f/6.f);
            #pragma unroll
            for (int j=0;j<8;j++){
                size_t base = (size_t)(r0+j)*64 + t;
                float hv = d_h[base] + scp*d_acch[base];
                float zv = d_z[base] + scp*d_accz[base];
                d_h[base] = hv; d_z[base] = zv;
                sh[j*64+t] = hv; sz[j*64+t] = zv;
            }
        }
    } else {
        #pragma unroll
        for (int j=0;j<8;j++){
            size_t base = (size_t)(r0+j)*64 + t;
            sh[j*64+t] = d_h[base] + c*d_kh[base];
            sz[j*64+t] = d_z[base] + c*d_kz[base];
        }
    }
    __syncthreads();

    float af[8], ag[8];
    float bf = fbin[t], bg = gbin[t];
    #pragma unroll
    for (int j=0;j<8;j++){ af[j]=bf; ag[j]=bg; }
    #pragma unroll 8
    for (int i=0;i<64;i++){
        float wf = fWin[i*64+t];
        float wg = gWin[i*64+t];
        #pragma unroll
        for (int j=0;j<8;j++){
            af[j] = fmaf(sh[j*64+i], wf, af[j]);
            ag[j] = fmaf(sz[j*64+i], wg, ag[j]);
        }
    }
    #pragma unroll
    for (int j=0;j<8;j++){
        int r = r0+j;
        int b = r/Nn, n = r - b*Nn;
        d_x1gT[(size_t)n*1024 + b*64 + t] = fmaxf(ag[j], 0.f);
    }
    #pragma unroll
    for (int j=0;j<8;j++) sx[j*64+t] = fmaxf(af[j], 0.f);
    __syncthreads();

    float bm = fbmid[t];
    #pragma unroll
    for (int j=0;j<8;j++) af[j]=bm;
    #pragma unroll 8
    for (int i=0;i<64;i++){
        float wf = fWmid[i*64+t];
        #pragma unroll
        for (int j=0;j<8;j++) af[j] = fmaf(sx[j*64+i], wf, af[j]);
    }
    __syncthreads();
    #pragma unroll
    for (int j=0;j<8;j++) sz[j*64+t] = fmaxf(af[j], 0.f);
    __syncthreads();

    float2 b3 = ((const float2*)fbout)[t];
    float2 a3[8];
    #pragma unroll
    for (int j=0;j<8;j++) a3[j]=b3;
    #pragma unroll 8
    for (int i=0;i<64;i++){
        float2 wv = ((const float2*)fWout)[i*64 + t];
        #pragma unroll
        for (int j=0;j<8;j++){
            a3[j].x = fmaf(sz[j*64+i], wv.x, a3[j].x);
            a3[j].y = fmaf(sz[j*64+i], wv.y, a3[j].y);
        }
    }

    int idx = 0;
    #pragma unroll
    for (int jj=1; jj<=NSTEP-1; jj++) if (times[jj] <= tv) idx = jj;
    float frac = tv - times[idx];
    #pragma unroll
    for (int j=0;j<8;j++){
        size_t cbase = ((size_t)(r0+j)*NSTEP + idx)*2;
        float dX0 = cb[cbase]   + (cc[cbase]   + cd[cbase]  *frac)*frac;
        float dX1 = cb[cbase+1] + (cc[cbase+1] + cd[cbase+1]*frac)*frac;
        float dh = fast_tanh(a3[j].x)*dX0 + fast_tanh(a3[j].y)*dX1;
        size_t base = (size_t)(r0+j)*64 + t;
        d_kh[base] = dh;
        d_acch[base] = (stage==0) ? dh : (d_acch[base] + w*dh);
    }
}

// graph aggregation GEMM: yT[307,1024] = A[307,320] @ x1gT[320,1024]
// 16x128 tiles, grid (20,8) = 160 blocks.
#define AGG_SMEM ((64*16*2 + 64*128)*4)   // As2 dup 8KB + Xs 32KB
__global__ void __launch_bounds__(256) k_agg(){
    extern __shared__ float sm[];
    float2* As2 = (float2*)sm;          // [k][16 rows] duplicated
    float*  Xs  = sm + 64*16*2;         // [k][128]
    int tid = threadIdx.x;
    int n0 = blockIdx.x * 16;
    int c0 = blockIdx.y * 128;
    int tx = tid & 31, ty = tid >> 5;   // ty: 8 groups x 2 rows

    ull acc[2][2];
    acc[0][0]=0ull; acc[0][1]=0ull; acc[1][0]=0ull; acc[1][1]=0ull;

    for (int kb = 0; kb < AGK; kb += 64){
        __syncthreads();
        {   // A tile: 16 rows x 64 k = 256 float4
            int rr = tid >> 4, k4 = tid & 15;
            float4 v = *(const float4*)&d_A[(size_t)(n0+rr)*AGK + kb + k4*4];
            As2[(k4*4+0)*16 + rr] = make_float2(v.x,v.x);
            As2[(k4*4+1)*16 + rr] = make_float2(v.y,v.y);
            As2[(k4*4+2)*16 + rr] = make_float2(v.z,v.z);
            As2[(k4*4+3)*16 + rr] = make_float2(v.w,v.w);
        }
        #pragma unroll
        for (int it=0; it<8; it++){
            int u = it*256 + tid;            // 2048 float4 = 64 k x 128 c
            int kk = u >> 5, c4 = u & 31;
            *(float4*)&Xs[kk*128 + c4*4] =
                *(const float4*)&d_x1gT[(size_t)(kb+kk)*1024 + c0 + c4*4];
        }
        __syncthreads();

        #pragma unroll 4
        for (int k=0;k<64;k++){
            float4 bv = *(const float4*)&Xs[k*128 + tx*4];
            ull b0,b1;
            asm("mov.b64 %0,{%1,%2};" : "=l"(b0) : "f"(bv.x), "f"(bv.y));
            asm("mov.b64 %0,{%1,%2};" : "=l"(b1) : "f"(bv.z), "f"(bv.w));
            const ull* Ar = (const ull*)&As2[k*16 + ty*2];
            ull a0 = Ar[0], a1 = Ar[1];
            asm("fma.rn.f32x2 %0, %1, %2, %0;" : "+l"(acc[0][0]) : "l"(a0), "l"(b0));
            asm("fma.rn.f32x2 %0, %1, %2, %0;" : "+l"(acc[0][1]) : "l"(a0), "l"(b1));
            asm("fma.rn.f32x2 %0, %1, %2, %0;" : "+l"(acc[1][0]) : "l"(a1), "l"(b0));
            asm("fma.rn.f32x2 %0, %1, %2, %0;" : "+l"(acc[1][1]) : "l"(a1), "l"(b1));
        }
    }
    #pragma unroll
    for (int i=0;i<2;i++){
        int n = n0 + ty*2 + i;
        if (n < Nn){
            float4 v;
            asm("mov.b64 {%0,%1},%2;" : "=f"(v.x), "=f"(v.y) : "l"(acc[i][0]));
            asm("mov.b64 {%0,%1},%2;" : "=f"(v.z), "=f"(v.w) : "l"(acc[i][1]));
            *(float4*)&d_yT[(size_t)n*1024 + c0 + tx*4] = v;
        }
    }
}

// AGC per node: smem-staged weights, f32x2 compute.
__global__ void __launch_bounds__(256) k_x2(){
    __shared__ float sw[8192];          // W0 [64i][64o] then W1
    __shared__ float sxs[1024];
    __shared__ float sys[1024];
    int n = blockIdx.x, tid = threadIdx.x;
    const float4* Wg = (const float4*)&d_agcW[(size_t)n*8192];
    float4* sw4 = (float4*)sw;
    #pragma unroll
    for (int it=0; it<8; it++) sw4[it*256 + tid] = Wg[it*256 + tid];
    ((float4*)sxs)[tid] = ((const float4*)&d_x1gT[(size_t)n*1024])[tid];
    ((float4*)sys)[tid] = ((const float4*)&d_yT[(size_t)n*1024])[tid];
    __syncthreads();

    int o4 = tid & 15, b = tid >> 4;
    float4 bias = *(const float4*)&d_agcb[n*64 + o4*4];
    ull acc0, acc1;
    asm("mov.b64 %0,{%1,%2};" : "=l"(acc0) : "f"(bias.x), "f"(bias.y));
    asm("mov.b64 %0,{%1,%2};" : "=l"(acc1) : "f"(bias.z), "f"(bias.w));
    const ull* W0p = (const ull*)sw;            // [i*32 + o4*2]
    const ull* W1p = (const ull*)(sw + 4096);
    const float* xr = &sxs[b*64];
    const float* yr = &sys[b*64];
    #pragma unroll 8
    for (int i=0;i<64;i++){
        ull w00 = W0p[i*32 + o4*2], w01 = W0p[i*32 + o4*2 + 1];
        ull w10 = W1p[i*32 + o4*2], w11 = W1p[i*32 + o4*2 + 1];
        float xv = xr[i], yv = yr[i];
        ull xx, yy;
        asm("mov.b64 %0,{%1,%1};" : "=l"(xx) : "f"(xv));
        asm("mov.b64 %0,{%1,%1};" : "=l"(yy) : "f"(yv));
        asm("fma.rn.f32x2 %0, %1, %2, %0;" : "+l"(acc0) : "l"(w00), "l"(xx));
        asm("fma.rn.f32x2 %0, %1, %2, %0;" : "+l"(acc1) : "l"(w01), "l"(xx));
        asm("fma.rn.f32x2 %0, %1, %2, %0;" : "+l"(acc0) : "l"(w10), "l"(yy));
        asm("fma.rn.f32x2 %0, %1, %2, %0;" : "+l"(acc1) : "l"(w11), "l"(yy));
    }
    float4 r;
    asm("mov.b64 {%0,%1},%2;" : "=f"(r.x), "=f"(r.y) : "l"(acc0));
    asm("mov.b64 {%0,%1},%2;" : "=f"(r.z), "=f"(r.w) : "l"(acc1));
    r.x = fmaxf(r.x,0.f); r.y = fmaxf(r.y,0.f);
    r.z = fmaxf(r.z,0.f); r.w = fmaxf(r.w,0.f);
    *(float4*)&d_x2[((size_t)b*Nn + n)*64 + o4*4] = r;
}

// big fused GEMM+tanh+contract (unchanged)
#define GZ_X2STRIDE 130
#define GZ_SMEM ((64*GZ_X2STRIDE*2 + 64*256 + 256)*4)

__global__ void __launch_bounds__(512) k_gz(
                     const float* __restrict__ gWout, const float* __restrict__ gbout,
                     int stage){
    extern __shared__ float sm[];
    float2* Xs2 = (float2*)sm;
    float* Ws = sm + 64*GZ_X2STRIDE*2;
    float* sb = Ws + 64*256;
    int tid = threadIdx.x;
    int r0 = blockIdx.x * 128;
    int c0 = blockIdx.y * 256;

    #pragma unroll
    for (int it=0; it<4; it++){
        int u = it*512 + tid;
        int row = u >> 4, kq = u & 15;
        int r = r0 + row;
        float4 v = (r < Rr) ? *(const float4*)&d_x2[(size_t)r*64 + kq*4]
                            : make_float4(0.f,0.f,0.f,0.f);
        Xs2[(kq*4+0)*GZ_X2STRIDE + row] = make_float2(v.x, v.x);
        Xs2[(kq*4+1)*GZ_X2STRIDE + row] = make_float2(v.y, v.y);
        Xs2[(kq*4+2)*GZ_X2STRIDE + row] = make_float2(v.z, v.z);
        Xs2[(kq*4+3)*GZ_X2STRIDE + row] = make_float2(v.w, v.w);
    }
    #pragma unroll
    for (int it=0; it<8; it++){
        int u = it*512 + tid;
        int k = u >> 6, c4 = u & 63;
        *(float4*)&Ws[k*256 + c4*4] = *(const float4*)&gWout[(size_t)k*4096 + c0 + c4*4];
    }
    if (tid < 256) sb[tid] = gbout[c0 + tid];
    __syncthreads();

    int tx = tid & 31, ty = tid >> 5;
    ull acc[8][4];
    #pragma unroll
    for (int i=0;i<8;i++)
        #pragma unroll
        for (int p=0;p<4;p++) acc[i][p] = 0ull;

    #pragma unroll 2
    for (int k=0;k<64;k++){
        float4 bA  = *(const float4*)&Ws[k*256 + tx*4];
        float4 bB  = *(const float4*)&Ws[k*256 + 128 + tx*4];
        ull b0,b1,b2,b3;
        asm("mov.b64 %0,{%1,%2};" : "=l"(b0) : "f"(bA.x), "f"(bA.y));
        asm("mov.b64 %0,{%1,%2};" : "=l"(b1) : "f"(bA.z), "f"(bA.w));
        asm("mov.b64 %0,{%1,%2};" : "=l"(b2) : "f"(bB.x), "f"(bB.y));
        asm("mov.b64 %0,{%1,%2};" : "=l"(b3) : "f"(bB.z), "f"(bB.w));
        const ull* Xrow = (const ull*)&Xs2[k*GZ_X2STRIDE + ty*8];
        #pragma unroll
        for (int i=0;i<8;i++){
            ull a2 = Xrow[i];
            asm("fma.rn.f32x2 %0, %1, %2, %0;" : "+l"(acc[i][0]) : "l"(a2), "l"(b0));
            asm("fma.rn.f32x2 %0, %1, %2, %0;" : "+l"(acc[i][1]) : "l"(a2), "l"(b1));
            asm("fma.rn.f32x2 %0, %1, %2, %0;" : "+l"(acc[i][2]) : "l"(a2), "l"(b2));
            asm("fma.rn.f32x2 %0, %1, %2, %0;" : "+l"(acc[i][3]) : "l"(a2), "l"(b3));
        }
    }

    float w = (stage==1 || stage==2) ? 2.f : 1.f;
    int jb = (4*tx) & 63;
    float bA0 = sb[4*tx],       bA1 = sb[4*tx+1];
    float bA2 = sb[4*tx+2],     bA3 = sb[4*tx+3];
    float bB0 = sb[128+4*tx],   bB1 = sb[128+4*tx+1];
    float bB2 = sb[128+4*tx+2], bB3 = sb[128+4*tx+3];
    float sA[8], sB[8];
    #pragma unroll
    for (int i=0;i<8;i++){
        int r = r0 + ty*8 + i;
        float4 dhv = make_float4(0.f,0.f,0.f,0.f);
        if (r < Rr) dhv = *(const float4*)&d_kh[(size_t)r*64 + jb];
        float g0,g1;
        asm("mov.b64 {%0,%1},%2;" : "=f"(g0), "=f"(g1) : "l"(acc[i][0]));
        float s = fast_tanh(g0+bA0)*dhv.x + fast_tanh(g1+bA1)*dhv.y;
        asm("mov.b64 {%0,%1},%2;" : "=f"(g0), "=f"(g1) : "l"(acc[i][1]));
        s += fast_tanh(g0+bA2)*dhv.z + fast_tanh(g1+bA3)*dhv.w;
        sA[i] = s;
        asm("mov.b64 {%0,%1},%2;" : "=f"(g0), "=f"(g1) : "l"(acc[i][2]));
        s = fast_tanh(g0+bB0)*dhv.x + fast_tanh(g1+bB1)*dhv.y;
        asm("mov.b64 {%0,%1},%2;" : "=f"(g0), "=f"(g1) : "l"(acc[i][3]));
        s += fast_tanh(g0+bB2)*dhv.z + fast_tanh(g1+bB3)*dhv.w;
        sB[i] = s;
    }
    #pragma unroll
    for (int s2=1; s2<16; s2<<=1){
        #pragma unroll
        for (int i=0;i<8;i++){
            sA[i] += __shfl_xor_sync(0xffffffffu, sA[i], s2);
            sB[i] += __shfl_xor_sync(0xffffffffu, sB[i], s2);
        }
    }
    if (tx == 0 || tx == 16){
        int ihalf = (tx == 16) ? 1 : 0;
        int iA = blockIdx.y*4 + ihalf;
        int iB = iA + 2;
        #pragma unroll
        for (int i=0;i<8;i++){
            int r = r0 + ty*8 + i;
            if (r < Rr){
                size_t oA = (size_t)r*64 + iA;
                size_t oB = (size_t)r*64 + iB;
                d_kz[oA] = sA[i];
                d_kz[oB] = sB[i];
                d_accz[oA] = (stage==0) ? sA[i] : (d_accz[oA] + w*sA[i]);
                d_accz[oB] = (stage==0) ? sB[i] : (d_accz[oB] + w*sB[i]);
            }
        }
    }
}

// output conv; applies the final RK4 update to z
__global__ void k_out(const float* __restrict__ convW, const float* __restrict__ convb,
                      const float* __restrict__ times, float* __restrict__ out){
    __shared__ float szr[64];
    int r = blockIdx.x, t = threadIdx.x;
    float sc = (times[NSTEP] - times[NSTEP-1]) * (1.f/6.f);
    size_t base = (size_t)r*64 + t;
    szr[t] = d_z[base] + sc*d_accz[base];
    __syncthreads();
    if (t < 12){
        float acc = convb[t];
        #pragma unroll 8
        for (int h=0; h<64; h++) acc = fmaf(szr[h], convW[t*64+h], acc);
        int b = r / Nn, n = r - b*Nn;
        out[(size_t)(b*12 + t)*Nn + n] = acc;
    }
}

// ---------------- launcher ----------------
extern "C" void kernel_launch(void* const* d_in, const int* in_sizes, int n_in,
                              void* d_out, int out_size){
    const float* coeff_a = (const float*)d_in[0];
    const float* coeff_b = (const float*)d_in[1];
    const float* coeff_c = (const float*)d_in[2];
    const float* coeff_d = (const float*)d_in[3];
    const float* times   = (const float*)d_in[4];
    const float* h_W     = (const float*)d_in[5];
    const float* h_b     = (const float*)d_in[6];
    const float* z_W     = (const float*)d_in[7];
    const float* z_b     = (const float*)d_in[8];
    const float* f_W_in  = (const float*)d_in[9];
    const float* f_b_in  = (const float*)d_in[10];
    const float* f_W_mid = (const float*)d_in[11];
    const float* f_b_mid = (const float*)d_in[12];
    const float* f_W_out = (const float*)d_in[13];
    const float* f_b_out = (const float*)d_in[14];
    const float* g_W_in  = (const float*)d_in[15];
    const float* g_b_in  = (const float*)d_in[16];
    const float* g_E     = (const float*)d_in[17];
    const float* g_Wpool = (const float*)d_in[18];
    const float* g_bpool = (const float*)d_in[19];
    const float* g_W_out = (const float*)d_in[20];
    const float* g_b_out = (const float*)d_in[21];
    const float* conv_W  = (const float*)d_in[22];
    const float* conv_b  = (const float*)d_in[23];
    float* out = (float*)d_out;

    cudaFuncSetAttribute(k_agg, cudaFuncAttributeMaxDynamicSharedMemorySize, AGG_SMEM);
    cudaFuncSetAttribute(k_gz,  cudaFuncAttributeMaxDynamicSharedMemorySize, GZ_SMEM);

    k_pre<<<Nn + PRE_AGCB_BLKS + PRE_AGCW_BLKS, 256>>>(g_E, g_bpool, g_Wpool);

    for (int step = 0; step < NSTEP; step++){
        for (int stage = 0; stage < 4; stage++){
            k_fg1<<<Rr/8, 64>>>(times, coeff_a, coeff_b, coeff_c, coeff_d,
                                h_W, h_b, z_W, z_b,
                                f_W_in, f_b_in, f_W_mid, f_b_mid, f_W_out, f_b_out,
                                g_W_in, g_b_in, step, stage);
            k_agg<<<dim3(20,8), 256, AGG_SMEM>>>();
            k_x2<<<Nn, 256>>>();
            k_gz<<<dim3(39,16), 512, GZ_SMEM>>>(g_W_out, g_b_out, stage);
        }
    }
    k_out<<<Rr, 64>>>(conv_W, conv_b, times, out);
}

// round 6
// speedup vs baseline: 1.0868x; 1.0868x over previous
#include <cuda_runtime.h>
#include <cstdint>
#include <cstddef>

#define Bb 16
#define Nn 307
#define NSTEP 11
#define Rr (Bb*Nn)   // 4912
#define AGK 320      // padded GEMM K / A stride
typedef unsigned long long ull;

// ---------------- device scratch (zero-initialized; pads never written) ----------------
__device__ float d_A[AGK*AGK];          // [320][320]; rows/cols >=307 stay 0
__device__ float d_agcW[(size_t)Nn*2*64*64];
__device__ float d_agcb[Nn*64];
__device__ float d_h[Rr*64];
__device__ float d_z[Rr*64];
__device__ float d_kh[Rr*64];
__device__ float d_kz[Rr*64];
__device__ float d_acch[Rr*64];
__device__ float d_accz[Rr*64];
__device__ float d_x1gT[(size_t)AGK*1024];  // [m][b*64+i]; rows >=307 stay 0
__device__ float d_yT[(size_t)Nn*1024];
__device__ float d_x2[Rr*64];

__device__ __forceinline__ float fast_tanh(float x){
    return 1.f - __fdividef(2.f, __expf(2.f*x) + 1.f);
}

// ---------------- fused precompute ----------------
#define PRE_AGCB_BLKS ((Nn*64 + 255)/256)
#define PRE_AGCW_BLKS ((Nn*8192 + 255)/256)
__global__ void k_pre(const float* __restrict__ gE,
                      const float* __restrict__ gbpool,
                      const float* __restrict__ gWpool){
    int tid = threadIdx.x;
    if (blockIdx.x < Nn){
        __shared__ float s[Nn];
        __shared__ float red[256];
        int n = blockIdx.x;
        float en[8];
        #pragma unroll
        for (int d=0; d<8; d++) en[d] = gE[n*8+d];
        for (int m=tid; m<Nn; m+=256){
            float acc = 0.f;
            #pragma unroll
            for (int d=0; d<8; d++) acc += en[d]*gE[m*8+d];
            s[m] = fmaxf(acc, 0.f);
        }
        __syncthreads();
        float mx = -1e30f;
        for (int m=tid; m<Nn; m+=256) mx = fmaxf(mx, s[m]);
        red[tid] = mx; __syncthreads();
        for (int o=128;o>0;o>>=1){ if (tid<o) red[tid]=fmaxf(red[tid],red[tid+o]); __syncthreads(); }
        mx = red[0]; __syncthreads();
        float sum = 0.f;
        for (int m=tid; m<Nn; m+=256){ float e = expf(s[m]-mx); s[m]=e; sum+=e; }
        red[tid]=sum; __syncthreads();
        for (int o=128;o>0;o>>=1){ if (tid<o) red[tid]+=red[tid+o]; __syncthreads(); }
        float inv = 1.f/red[0];
        for (int m=tid; m<Nn; m+=256) d_A[(size_t)n*AGK+m] = s[m]*inv;
    } else if (blockIdx.x < Nn + PRE_AGCB_BLKS){
        int idx = (blockIdx.x - Nn)*256 + tid;
        if (idx < Nn*64){
            int n = idx >> 6, o = idx & 63;
            float acc = 0.f;
            #pragma unroll
            for (int d=0; d<8; d++) acc += gE[n*8+d]*gbpool[d*64+o];
            d_agcb[idx] = acc;
        }
    } else {
        int idx = (blockIdx.x - Nn - PRE_AGCB_BLKS)*256 + tid;
        if (idx < Nn*8192){
            int n = idx >> 13;
            int rest = idx & 8191;
            float acc = 0.f;
            #pragma unroll
            for (int d=0; d<8; d++) acc += gE[n*8+d]*gWpool[(size_t)d*8192 + rest];
            d_agcW[idx] = acc;
        }
    }
}

// ---------------- per-stage kernels ----------------
__global__ void __launch_bounds__(64) k_fg1(
                      const float* __restrict__ times,
                      const float* __restrict__ coeff_a,
                      const float* __restrict__ cb, const float* __restrict__ cc, const float* __restrict__ cd,
                      const float* __restrict__ hW, const float* __restrict__ hb,
                      const float* __restrict__ zW, const float* __restrict__ zb,
                      const float* __restrict__ fWin, const float* __restrict__ fbin,
                      const float* __restrict__ fWmid, const float* __restrict__ fbmid,
                      const float* __restrict__ fWout, const float* __restrict__ fbout,
                      const float* __restrict__ gWin, const float* __restrict__ gbin,
                      int step, int stage){
    int t = threadIdx.x;
    int r0 = blockIdx.x * 8;
    __shared__ float sh[8*64], sz[8*64], sx[8*64];

    float t0 = times[step], t1 = times[step+1];
    float dt = t1 - t0;
    float c  = (stage==0) ? 0.f : ((stage==3) ? dt : 0.5f*dt);
    float tv = (stage==0) ? t0  : ((stage==3) ? t1 : (t0 + 0.5f*dt));
    float w  = (stage==1 || stage==2) ? 2.f : 1.f;

    if (stage == 0){
        if (step == 0){
            float wh0 = hW[t], wh1 = hW[64+t], bh = hb[t];
            float wz0 = zW[t], wz1 = zW[64+t], bz = zb[t];
            #pragma unroll
            for (int j=0;j<8;j++){
                int r = r0+j;
                float x0 = coeff_a[(size_t)r*(NSTEP*2) + 0];
                float x1 = coeff_a[(size_t)r*(NSTEP*2) + 1];
                float hv = x0*wh0 + x1*wh1 + bh;
                float zv = x0*wz0 + x1*wz1 + bz;
                size_t base = (size_t)r*64 + t;
                d_h[base] = hv; d_z[base] = zv;
                sh[j*64+t] = hv; sz[j*64+t] = zv;
            }
        } else {
            float scp = (times[step] - times[step-1]) * (1.f/6.f);
            #pragma unroll
            for (int j=0;j<8;j++){
                size_t base = (size_t)(r0+j)*64 + t;
                float hv = d_h[base] + scp*d_acch[base];
                float zv = d_z[base] + scp*d_accz[base];
                d_h[base] = hv; d_z[base] = zv;
                sh[j*64+t] = hv; sz[j*64+t] = zv;
            }
        }
    } else {
        #pragma unroll
        for (int j=0;j<8;j++){
            size_t base = (size_t)(r0+j)*64 + t;
            sh[j*64+t] = d_h[base] + c*d_kh[base];
            sz[j*64+t] = d_z[base] + c*d_kz[base];
        }
    }
    __syncthreads();

    float af[8], ag[8];
    float bf = fbin[t], bg = gbin[t];
    #pragma unroll
    for (int j=0;j<8;j++){ af[j]=bf; ag[j]=bg; }
    #pragma unroll 8
    for (int i=0;i<64;i++){
        float wf = fWin[i*64+t];
        float wg = gWin[i*64+t];
        #pragma unroll
        for (int j=0;j<8;j++){
            af[j] = fmaf(sh[j*64+i], wf, af[j]);
            ag[j] = fmaf(sz[j*64+i], wg, ag[j]);
        }
    }
    #pragma unroll
    for (int j=0;j<8;j++){
        int r = r0+j;
        int b = r/Nn, n = r - b*Nn;
        d_x1gT[(size_t)n*1024 + b*64 + t] = fmaxf(ag[j], 0.f);
    }
    #pragma unroll
    for (int j=0;j<8;j++) sx[j*64+t] = fmaxf(af[j], 0.f);
    __syncthreads();

    float bm = fbmid[t];
    #pragma unroll
    for (int j=0;j<8;j++) af[j]=bm;
    #pragma unroll 8
    for (int i=0;i<64;i++){
        float wf = fWmid[i*64+t];
        #pragma unroll
        for (int j=0;j<8;j++) af[j] = fmaf(sx[j*64+i], wf, af[j]);
    }
    __syncthreads();
    #pragma unroll
    for (int j=0;j<8;j++) sz[j*64+t] = fmaxf(af[j], 0.f);
    __syncthreads();

    float2 b3 = ((const float2*)fbout)[t];
    float2 a3[8];
    #pragma unroll
    for (int j=0;j<8;j++) a3[j]=b3;
    #pragma unroll 8
    for (int i=0;i<64;i++){
        float2 wv = ((const float2*)fWout)[i*64 + t];
        #pragma unroll
        for (int j=0;j<8;j++){
            a3[j].x = fmaf(sz[j*64+i], wv.x, a3[j].x);
            a3[j].y = fmaf(sz[j*64+i], wv.y, a3[j].y);
        }
    }

    int idx = 0;
    #pragma unroll
    for (int jj=1; jj<=NSTEP-1; jj++) if (times[jj] <= tv) idx = jj;
    float frac = tv - times[idx];
    #pragma unroll
    for (int j=0;j<8;j++){
        size_t cbase = ((size_t)(r0+j)*NSTEP + idx)*2;
        float dX0 = cb[cbase]   + (cc[cbase]   + cd[cbase]  *frac)*frac;
        float dX1 = cb[cbase+1] + (cc[cbase+1] + cd[cbase+1]*frac)*frac;
        float dh = fast_tanh(a3[j].x)*dX0 + fast_tanh(a3[j].y)*dX1;
        size_t base = (size_t)(r0+j)*64 + t;
        d_kh[base] = dh;
        d_acch[base] = (stage==0) ? dh : (d_acch[base] + w*dh);
    }
}

// graph aggregation GEMM (R4 version): yT = A @ x1gT, 32x128 tiles, grid (10,8)
#define AGG_SMEM ((64*32*2 + 64*128)*4)   // As2 dup 16KB + Xs 32KB
__global__ void __launch_bounds__(256) k_agg(){
    extern __shared__ float sm[];
    float2* As2 = (float2*)sm;          // [k][row] duplicated, stride 32
    float*  Xs  = sm + 64*32*2;         // [k][128]
    int tid = threadIdx.x;
    int n0 = blockIdx.x * 32;
    int c0 = blockIdx.y * 128;
    int tx = tid & 31, ty = tid >> 5;

    ull acc[4][2];
    #pragma unroll
    for (int i=0;i<4;i++){ acc[i][0]=0ull; acc[i][1]=0ull; }

    for (int kb = 0; kb < AGK; kb += 64){
        __syncthreads();
        #pragma unroll
        for (int it=0; it<2; it++){
            int u = it*256 + tid;            // 512 float4 = 32 rows x 64 k
            int rr = u >> 4, k4 = u & 15;
            float4 v = *(const float4*)&d_A[(size_t)(n0+rr)*AGK + kb + k4*4];
            As2[(k4*4+0)*32 + rr] = make_float2(v.x,v.x);
            As2[(k4*4+1)*32 + rr] = make_float2(v.y,v.y);
            As2[(k4*4+2)*32 + rr] = make_float2(v.z,v.z);
            As2[(k4*4+3)*32 + rr] = make_float2(v.w,v.w);
        }
        #pragma unroll
        for (int it=0; it<8; it++){
            int u = it*256 + tid;            // 2048 float4 = 64 k x 128 c
            int kk = u >> 5, c4 = u & 31;
            *(float4*)&Xs[kk*128 + c4*4] =
                *(const float4*)&d_x1gT[(size_t)(kb+kk)*1024 + c0 + c4*4];
        }
        __syncthreads();

        #pragma unroll 4
        for (int k=0;k<64;k++){
            float4 bv = *(const float4*)&Xs[k*128 + tx*4];
            ull b0,b1;
            asm("mov.b64 %0,{%1,%2};" : "=l"(b0) : "f"(bv.x), "f"(bv.y));
            asm("mov.b64 %0,{%1,%2};" : "=l"(b1) : "f"(bv.z), "f"(bv.w));
            const ull* Ar = (const ull*)&As2[k*32 + ty*4];
            #pragma unroll
            for (int i=0;i<4;i++){
                ull a2 = Ar[i];
                asm("fma.rn.f32x2 %0, %1, %2, %0;" : "+l"(acc[i][0]) : "l"(a2), "l"(b0));
                asm("fma.rn.f32x2 %0, %1, %2, %0;" : "+l"(acc[i][1]) : "l"(a2), "l"(b1));
            }
        }
    }
    #pragma unroll
    for (int i=0;i<4;i++){
        int n = n0 + ty*4 + i;
        if (n < Nn){
            float4 v;
            asm("mov.b64 {%0,%1},%2;" : "=f"(v.x), "=f"(v.y) : "l"(acc[i][0]));
            asm("mov.b64 {%0,%1},%2;" : "=f"(v.z), "=f"(v.w) : "l"(acc[i][1]));
            *(float4*)&d_yT[(size_t)n*1024 + c0 + tx*4] = v;
        }
    }
}

// AGC per node, split into 2 blocks per node (half of o each) for latency hiding.
__global__ void __launch_bounds__(128) k_x2(){
    __shared__ float sw0[64*32];        // W0 cols [half*32, half*32+32)
    __shared__ float sw1[64*32];
    __shared__ float sxs[1024];
    __shared__ float sys[1024];
    int n = blockIdx.x, half = blockIdx.y;
    int tid = threadIdx.x;
    const float4* Wg = (const float4*)&d_agcW[(size_t)n*8192];
    float4* s0 = (float4*)sw0;
    float4* s1 = (float4*)sw1;
    #pragma unroll
    for (int it=0; it<4; it++){
        int u = it*128 + tid;            // 512 float4 per W half
        int i = u >> 3, c4 = u & 7;
        s0[u] = Wg[i*16 + half*8 + c4];
        s1[u] = Wg[1024 + i*16 + half*8 + c4];
    }
    #pragma unroll
    for (int it=0; it<2; it++){
        int u = it*128 + tid;
        ((float4*)sxs)[u] = ((const float4*)&d_x1gT[(size_t)n*1024])[u];
        ((float4*)sys)[u] = ((const float4*)&d_yT[(size_t)n*1024])[u];
    }
    __syncthreads();

    int o4 = tid & 7, b = tid >> 3;      // 8 o-quads x 16 batches
    float4 bias = *(const float4*)&d_agcb[n*64 + half*32 + o4*4];
    ull acc0, acc1;
    asm("mov.b64 %0,{%1,%2};" : "=l"(acc0) : "f"(bias.x), "f"(bias.y));
    asm("mov.b64 %0,{%1,%2};" : "=l"(acc1) : "f"(bias.z), "f"(bias.w));
    const ull* W0p = (const ull*)sw0;    // [i*16 + o4*2]
    const ull* W1p = (const ull*)sw1;
    const float* xr = &sxs[b*64];
    const float* yr = &sys[b*64];
    #pragma unroll 8
    for (int i=0;i<64;i++){
        ull w00 = W0p[i*16 + o4*2], w01 = W0p[i*16 + o4*2 + 1];
        ull w10 = W1p[i*16 + o4*2], w11 = W1p[i*16 + o4*2 + 1];
        float xv = xr[i], yv = yr[i];
        ull xx, yy;
        asm("mov.b64 %0,{%1,%1};" : "=l"(xx) : "f"(xv));
        asm("mov.b64 %0,{%1,%1};" : "=l"(yy) : "f"(yv));
        asm("fma.rn.f32x2 %0, %1, %2, %0;" : "+l"(acc0) : "l"(w00), "l"(xx));
        asm("fma.rn.f32x2 %0, %1, %2, %0;" : "+l"(acc1) : "l"(w01), "l"(xx));
        asm("fma.rn.f32x2 %0, %1, %2, %0;" : "+l"(acc0) : "l"(w10), "l"(yy));
        asm("fma.rn.f32x2 %0, %1, %2, %0;" : "+l"(acc1) : "l"(w11), "l"(yy));
    }
    float4 r;
    asm("mov.b64 {%0,%1},%2;" : "=f"(r.x), "=f"(r.y) : "l"(acc0));
    asm("mov.b64 {%0,%1},%2;" : "=f"(r.z), "=f"(r.w) : "l"(acc1));
    r.x = fmaxf(r.x,0.f); r.y = fmaxf(r.y,0.f);
    r.z = fmaxf(r.z,0.f); r.w = fmaxf(r.w,0.f);
    *(float4*)&d_x2[((size_t)b*Nn + n)*64 + half*32 + o4*4] = r;
}

// big fused GEMM+tanh+contract (unchanged)
#define GZ_X2STRIDE 130
#define GZ_SMEM ((64*GZ_X2STRIDE*2 + 64*256 + 256)*4)

__global__ void __launch_bounds__(512) k_gz(
                     const float* __restrict__ gWout, const float* __restrict__ gbout,
                     int stage){
    extern __shared__ float sm[];
    float2* Xs2 = (float2*)sm;
    float* Ws = sm + 64*GZ_X2STRIDE*2;
    float* sb = Ws + 64*256;
    int tid = threadIdx.x;
    int r0 = blockIdx.x * 128;
    int c0 = blockIdx.y * 256;

    #pragma unroll
    for (int it=0; it<4; it++){
        int u = it*512 + tid;
        int row = u >> 4, kq = u & 15;
        int r = r0 + row;
        float4 v = (r < Rr) ? *(const float4*)&d_x2[(size_t)r*64 + kq*4]
                            : make_float4(0.f,0.f,0.f,0.f);
        Xs2[(kq*4+0)*GZ_X2STRIDE + row] = make_float2(v.x, v.x);
        Xs2[(kq*4+1)*GZ_X2STRIDE + row] = make_float2(v.y, v.y);
        Xs2[(kq*4+2)*GZ_X2STRIDE + row] = make_float2(v.z, v.z);
        Xs2[(kq*4+3)*GZ_X2STRIDE + row] = make_float2(v.w, v.w);
    }
    #pragma unroll
    for (int it=0; it<8; it++){
        int u = it*512 + tid;
        int k = u >> 6, c4 = u & 63;
        *(float4*)&Ws[k*256 + c4*4] = *(const float4*)&gWout[(size_t)k*4096 + c0 + c4*4];
    }
    if (tid < 256) sb[tid] = gbout[c0 + tid];
    __syncthreads();

    int tx = tid & 31, ty = tid >> 5;
    ull acc[8][4];
    #pragma unroll
    for (int i=0;i<8;i++)
        #pragma unroll
        for (int p=0;p<4;p++) acc[i][p] = 0ull;

    #pragma unroll 2
    for (int k=0;k<64;k++){
        float4 bA  = *(const float4*)&Ws[k*256 + tx*4];
        float4 bB  = *(const float4*)&Ws[k*256 + 128 + tx*4];
        ull b0,b1,b2,b3;
        asm("mov.b64 %0,{%1,%2};" : "=l"(b0) : "f"(bA.x), "f"(bA.y));
        asm("mov.b64 %0,{%1,%2};" : "=l"(b1) : "f"(bA.z), "f"(bA.w));
        asm("mov.b64 %0,{%1,%2};" : "=l"(b2) : "f"(bB.x), "f"(bB.y));
        asm("mov.b64 %0,{%1,%2};" : "=l"(b3) : "f"(bB.z), "f"(bB.w));
        const ull* Xrow = (const ull*)&Xs2[k*GZ_X2STRIDE + ty*8];
        #pragma unroll
        for (int i=0;i<8;i++){
            ull a2 = Xrow[i];
            asm("fma.rn.f32x2 %0, %1, %2, %0;" : "+l"(acc[i][0]) : "l"(a2), "l"(b0));
            asm("fma.rn.f32x2 %0, %1, %2, %0;" : "+l"(acc[i][1]) : "l"(a2), "l"(b1));
            asm("fma.rn.f32x2 %0, %1, %2, %0;" : "+l"(acc[i][2]) : "l"(a2), "l"(b2));
            asm("fma.rn.f32x2 %0, %1, %2, %0;" : "+l"(acc[i][3]) : "l"(a2), "l"(b3));
        }
    }

    float w = (stage==1 || stage==2) ? 2.f : 1.f;
    int jb = (4*tx) & 63;
    float bA0 = sb[4*tx],       bA1 = sb[4*tx+1];
    float bA2 = sb[4*tx+2],     bA3 = sb[4*tx+3];
    float bB0 = sb[128+4*tx],   bB1 = sb[128+4*tx+1];
    float bB2 = sb[128+4*tx+2], bB3 = sb[128+4*tx+3];
    float sA[8], sB[8];
    #pragma unroll
    for (int i=0;i<8;i++){
        int r = r0 + ty*8 + i;
        float4 dhv = make_float4(0.f,0.f,0.f,0.f);
        if (r < Rr) dhv = *(const float4*)&d_kh[(size_t)r*64 + jb];
        float g0,g1;
        asm("mov.b64 {%0,%1},%2;" : "=f"(g0), "=f"(g1) : "l"(acc[i][0]));
        float s = fast_tanh(g0+bA0)*dhv.x + fast_tanh(g1+bA1)*dhv.y;
        asm("mov.b64 {%0,%1},%2;" : "=f"(g0), "=f"(g1) : "l"(acc[i][1]));
        s += fast_tanh(g0+bA2)*dhv.z + fast_tanh(g1+bA3)*dhv.w;
        sA[i] = s;
        asm("mov.b64 {%0,%1},%2;" : "=f"(g0), "=f"(g1) : "l"(acc[i][2]));
        s = fast_tanh(g0+bB0)*dhv.x + fast_tanh(g1+bB1)*dhv.y;
        asm("mov.b64 {%0,%1},%2;" : "=f"(g0), "=f"(g1) : "l"(acc[i][3]));
        s += fast_tanh(g0+bB2)*dhv.z + fast_tanh(g1+bB3)*dhv.w;
        sB[i] = s;
    }
    #pragma unroll
    for (int s2=1; s2<16; s2<<=1){
        #pragma unroll
        for (int i=0;i<8;i++){
            sA[i] += __shfl_xor_sync(0xffffffffu, sA[i], s2);
            sB[i] += __shfl_xor_sync(0xffffffffu, sB[i], s2);
        }
    }
    if (tx == 0 || tx == 16){
        int ihalf = (tx == 16) ? 1 : 0;
        int iA = blockIdx.y*4 + ihalf;
        int iB = iA + 2;
        #pragma unroll
        for (int i=0;i<8;i++){
            int r = r0 + ty*8 + i;
            if (r < Rr){
                size_t oA = (size_t)r*64 + iA;
                size_t oB = (size_t)r*64 + iB;
                d_kz[oA] = sA[i];
                d_kz[oB] = sB[i];
                d_accz[oA] = (stage==0) ? sA[i] : (d_accz[oA] + w*sA[i]);
                d_accz[oB] = (stage==0) ? sB[i] : (d_accz[oB] + w*sB[i]);
            }
        }
    }
}

// output conv; applies the final RK4 update to z
__global__ void k_out(const float* __restrict__ convW, const float* __restrict__ convb,
                      const float* __restrict__ times, float* __restrict__ out){
    __shared__ float szr[64];
    int r = blockIdx.x, t = threadIdx.x;
    float sc = (times[NSTEP] - times[NSTEP-1]) * (1.f/6.f);
    size_t base = (size_t)r*64 + t;
    szr[t] = d_z[base] + sc*d_accz[base];
    __syncthreads();
    if (t < 12){
        float acc = convb[t];
        #pragma unroll 8
        for (int h=0; h<64; h++) acc = fmaf(szr[h], convW[t*64+h], acc);
        int b = r / Nn, n = r - b*Nn;
        out[(size_t)(b*12 + t)*Nn + n] = acc;
    }
}

// ---------------- launcher ----------------
extern "C" void kernel_launch(void* const* d_in, const int* in_sizes, int n_in,
                              void* d_out, int out_size){
    const float* coeff_a = (const float*)d_in[0];
    const float* coeff_b = (const float*)d_in[1];
    const float* coeff_c = (const float*)d_in[2];
    const float* coeff_d = (const float*)d_in[3];
    const float* times   = (const float*)d_in[4];
    const float* h_W     = (const float*)d_in[5];
    const float* h_b     = (const float*)d_in[6];
    const float* z_W     = (const float*)d_in[7];
    const float* z_b     = (const float*)d_in[8];
    const float* f_W_in  = (const float*)d_in[9];
    const float* f_b_in  = (const float*)d_in[10];
    const float* f_W_mid = (const float*)d_in[11];
    const float* f_b_mid = (const float*)d_in[12];
    const float* f_W_out = (const float*)d_in[13];
    const float* f_b_out = (const float*)d_in[14];
    const float* g_W_in  = (const float*)d_in[15];
    const float* g_b_in  = (const float*)d_in[16];
    const float* g_E     = (const float*)d_in[17];
    const float* g_Wpool = (const float*)d_in[18];
    const float* g_bpool = (const float*)d_in[19];
    const float* g_W_out = (const float*)d_in[20];
    const float* g_b_out = (const float*)d_in[21];
    const float* conv_W  = (const float*)d_in[22];
    const float* conv_b  = (const float*)d_in[23];
    float* out = (float*)d_out;

    cudaFuncSetAttribute(k_agg, cudaFuncAttributeMaxDynamicSharedMemorySize, AGG_SMEM);
    cudaFuncSetAttribute(k_gz,  cudaFuncAttributeMaxDynamicSharedMemorySize, GZ_SMEM);

    k_pre<<<Nn + PRE_AGCB_BLKS + PRE_AGCW_BLKS, 256>>>(g_E, g_bpool, g_Wpool);

    for (int step = 0; step < NSTEP; step++){
        for (int stage = 0; stage < 4; stage++){
            k_fg1<<<Rr/8, 64>>>(times, coeff_a, coeff_b, coeff_c, coeff_d,
                                h_W, h_b, z_W, z_b,
                                f_W_in, f_b_in, f_W_mid, f_b_mid, f_W_out, f_b_out,
                                g_W_in, g_b_in, step, stage);
            k_agg<<<dim3(10,8), 256, AGG_SMEM>>>();
            k_x2<<<dim3(Nn,2), 128>>>();
            k_gz<<<dim3(39,16), 512, GZ_SMEM>>>(g_W_out, g_b_out, stage);
        }
    }
    k_out<<<Rr, 64>>>(conv_W, conv_b, times, out);
}

// round 7
// speedup vs baseline: 1.2838x; 1.1812x over previous
#include <cuda_runtime.h>
#include <cstdint>
#include <cstddef>

#define Bb 16
#define Nn 307
#define NSTEP 11
#define Rr (Bb*Nn)   // 4912
#define AGK 320      // padded GEMM K / A stride
typedef unsigned long long ull;

// ---------------- device scratch (zero-initialized; pads never written) ----------------
__device__ float d_A[AGK*AGK];          // [320][320]; rows/cols >=307 stay 0
__device__ float d_agcW[(size_t)Nn*2*64*64];
__device__ float d_agcb[Nn*64];
__device__ float d_h[Rr*64];
__device__ float d_z[Rr*64];
__device__ float d_kh[Rr*64];
__device__ float d_kz[Rr*64];
__device__ float d_acch[Rr*64];
__device__ float d_accz[Rr*64];
__device__ float d_x1gT[(size_t)AGK*1024];  // [m][b*64+i]; rows >=307 stay 0
__device__ float d_yT[(size_t)Nn*1024];
__device__ float d_x2[Rr*64];

__device__ __forceinline__ float fast_tanh(float x){
    return 1.f - __fdividef(2.f, __expf(2.f*x) + 1.f);
}

// ---------------- per-stage kernels ----------------
// Normal blocks [0, Rr/8): 8 rows each, f-MLP + g layer1.
// First launch only: extra blocks do precompute (A softmax / agcb / agcW).
#define FG1_BLKS (Rr/8)                         // 614
#define PRE_A_BLKS Nn                           // 307
#define PRE_B_BLKS ((Nn*64 + 63)/64)            // 307
#define PRE_W_BLKS ((Nn*8192 + 255)/256)        // 9824 (4 elems/thread)
#define FG1_GRID_PRE (FG1_BLKS + PRE_A_BLKS + PRE_B_BLKS + PRE_W_BLKS)

__global__ void __launch_bounds__(64) k_fg1(
                      const float* __restrict__ times,
                      const float* __restrict__ coeff_a,
                      const float* __restrict__ cb, const float* __restrict__ cc, const float* __restrict__ cd,
                      const float* __restrict__ hW, const float* __restrict__ hb,
                      const float* __restrict__ zW, const float* __restrict__ zb,
                      const float* __restrict__ fWin, const float* __restrict__ fbin,
                      const float* __restrict__ fWmid, const float* __restrict__ fbmid,
                      const float* __restrict__ fWout, const float* __restrict__ fbout,
                      const float* __restrict__ gWin, const float* __restrict__ gbin,
                      const float* __restrict__ gE, const float* __restrict__ gbpool,
                      const float* __restrict__ gWpool,
                      int step, int stage){
    int t = threadIdx.x;

    if (blockIdx.x >= FG1_BLKS){
        // ---- precompute blocks (only present on the first launch) ----
        int pb = blockIdx.x - FG1_BLKS;
        if (pb < PRE_A_BLKS){
            // softmax(relu(gE[n] . gE[:]^T)) row
            __shared__ float s[Nn];
            __shared__ float red[64];
            int n = pb;
            float en[8];
            #pragma unroll
            for (int d=0; d<8; d++) en[d] = gE[n*8+d];
            for (int m=t; m<Nn; m+=64){
                float acc = 0.f;
                #pragma unroll
                for (int d=0; d<8; d++) acc += en[d]*gE[m*8+d];
                s[m] = fmaxf(acc, 0.f);
            }
            __syncthreads();
            float mx = -1e30f;
            for (int m=t; m<Nn; m+=64) mx = fmaxf(mx, s[m]);
            red[t] = mx; __syncthreads();
            for (int o=32;o>0;o>>=1){ if (t<o) red[t]=fmaxf(red[t],red[t+o]); __syncthreads(); }
            mx = red[0]; __syncthreads();
            float sum = 0.f;
            for (int m=t; m<Nn; m+=64){ float e = expf(s[m]-mx); s[m]=e; sum+=e; }
            red[t]=sum; __syncthreads();
            for (int o=32;o>0;o>>=1){ if (t<o) red[t]+=red[t+o]; __syncthreads(); }
            float inv = 1.f/red[0];
            for (int m=t; m<Nn; m+=64) d_A[(size_t)n*AGK+m] = s[m]*inv;
        } else if (pb < PRE_A_BLKS + PRE_B_BLKS){
            int idx = (pb - PRE_A_BLKS)*64 + t;
            if (idx < Nn*64){
                int n = idx >> 6, o = idx & 63;
                float acc = 0.f;
                #pragma unroll
                for (int d=0; d<8; d++) acc += gE[n*8+d]*gbpool[d*64+o];
                d_agcb[idx] = acc;
            }
        } else {
            int base = (pb - PRE_A_BLKS - PRE_B_BLKS)*256 + t*4;
            if (base < Nn*8192){
                int n = base >> 13;
                int rest = base & 8191;
                float4 acc = make_float4(0.f,0.f,0.f,0.f);
                #pragma unroll
                for (int d=0; d<8; d++){
                    float e = gE[n*8+d];
                    float4 wv = *(const float4*)&gWpool[(size_t)d*8192 + rest];
                    acc.x += e*wv.x; acc.y += e*wv.y;
                    acc.z += e*wv.z; acc.w += e*wv.w;
                }
                *(float4*)&d_agcW[base] = acc;
            }
        }
        return;
    }

    int r0 = blockIdx.x * 8;
    __shared__ float sh[8*64], sz[8*64], sx[8*64];

    float t0 = times[step], t1 = times[step+1];
    float dt = t1 - t0;
    float c  = (stage==0) ? 0.f : ((stage==3) ? dt : 0.5f*dt);
    float tv = (stage==0) ? t0  : ((stage==3) ? t1 : (t0 + 0.5f*dt));
    float w  = (stage==1 || stage==2) ? 2.f : 1.f;

    if (stage == 0){
        if (step == 0){
            float wh0 = hW[t], wh1 = hW[64+t], bh = hb[t];
            float wz0 = zW[t], wz1 = zW[64+t], bz = zb[t];
            #pragma unroll
            for (int j=0;j<8;j++){
                int r = r0+j;
                float x0 = coeff_a[(size_t)r*(NSTEP*2) + 0];
                float x1 = coeff_a[(size_t)r*(NSTEP*2) + 1];
                float hv = x0*wh0 + x1*wh1 + bh;
                float zv = x0*wz0 + x1*wz1 + bz;
                size_t base = (size_t)r*64 + t;
                d_h[base] = hv; d_z[base] = zv;
                sh[j*64+t] = hv; sz[j*64+t] = zv;
            }
        } else {
            float scp = (times[step] - times[step-1]) * (1.f/6.f);
            #pragma unroll
            for (int j=0;j<8;j++){
                size_t base = (size_t)(r0+j)*64 + t;
                float hv = d_h[base] + scp*d_acch[base];
                float zv = d_z[base] + scp*d_accz[base];
                d_h[base] = hv; d_z[base] = zv;
                sh[j*64+t] = hv; sz[j*64+t] = zv;
            }
        }
    } else {
        #pragma unroll
        for (int j=0;j<8;j++){
            size_t base = (size_t)(r0+j)*64 + t;
            sh[j*64+t] = d_h[base] + c*d_kh[base];
            sz[j*64+t] = d_z[base] + c*d_kz[base];
        }
    }
    __syncthreads();

    float af[8], ag[8];
    float bf = fbin[t], bg = gbin[t];
    #pragma unroll
    for (int j=0;j<8;j++){ af[j]=bf; ag[j]=bg; }
    #pragma unroll 8
    for (int i=0;i<64;i++){
        float wf = fWin[i*64+t];
        float wg = gWin[i*64+t];
        #pragma unroll
        for (int j=0;j<8;j++){
            af[j] = fmaf(sh[j*64+i], wf, af[j]);
            ag[j] = fmaf(sz[j*64+i], wg, ag[j]);
        }
    }
    #pragma unroll
    for (int j=0;j<8;j++){
        int r = r0+j;
        int b = r/Nn, n = r - b*Nn;
        d_x1gT[(size_t)n*1024 + b*64 + t] = fmaxf(ag[j], 0.f);
    }
    #pragma unroll
    for (int j=0;j<8;j++) sx[j*64+t] = fmaxf(af[j], 0.f);
    __syncthreads();

    float bm = fbmid[t];
    #pragma unroll
    for (int j=0;j<8;j++) af[j]=bm;
    #pragma unroll 8
    for (int i=0;i<64;i++){
        float wf = fWmid[i*64+t];
        #pragma unroll
        for (int j=0;j<8;j++) af[j] = fmaf(sx[j*64+i], wf, af[j]);
    }
    __syncthreads();
    #pragma unroll
    for (int j=0;j<8;j++) sz[j*64+t] = fmaxf(af[j], 0.f);
    __syncthreads();

    float2 b3 = ((const float2*)fbout)[t];
    float2 a3[8];
    #pragma unroll
    for (int j=0;j<8;j++) a3[j]=b3;
    #pragma unroll 8
    for (int i=0;i<64;i++){
        float2 wv = ((const float2*)fWout)[i*64 + t];
        #pragma unroll
        for (int j=0;j<8;j++){
            a3[j].x = fmaf(sz[j*64+i], wv.x, a3[j].x);
            a3[j].y = fmaf(sz[j*64+i], wv.y, a3[j].y);
        }
    }

    int idx = 0;
    #pragma unroll
    for (int jj=1; jj<=NSTEP-1; jj++) if (times[jj] <= tv) idx = jj;
    float frac = tv - times[idx];
    #pragma unroll
    for (int j=0;j<8;j++){
        size_t cbase = ((size_t)(r0+j)*NSTEP + idx)*2;
        float dX0 = cb[cbase]   + (cc[cbase]   + cd[cbase]  *frac)*frac;
        float dX1 = cb[cbase+1] + (cc[cbase+1] + cd[cbase+1]*frac)*frac;
        float dh = fast_tanh(a3[j].x)*dX0 + fast_tanh(a3[j].y)*dX1;
        size_t base = (size_t)(r0+j)*64 + t;
        d_kh[base] = dh;
        d_acch[base] = (stage==0) ? dh : (d_acch[base] + w*dh);
    }
}

// graph aggregation GEMM: yT = A @ x1gT, 32x128 tiles, grid (10,8)
#define AGG_SMEM ((64*32*2 + 64*128)*4)   // As2 dup 16KB + Xs 32KB
__global__ void __launch_bounds__(256) k_agg(){
    extern __shared__ float sm[];
    float2* As2 = (float2*)sm;          // [k][row] duplicated, stride 32
    float*  Xs  = sm + 64*32*2;         // [k][128]
    int tid = threadIdx.x;
    int n0 = blockIdx.x * 32;
    int c0 = blockIdx.y * 128;
    int tx = tid & 31, ty = tid >> 5;

    ull acc[4][2];
    #pragma unroll
    for (int i=0;i<4;i++){ acc[i][0]=0ull; acc[i][1]=0ull; }

    for (int kb = 0; kb < AGK; kb += 64){
        __syncthreads();
        #pragma unroll
        for (int it=0; it<2; it++){
            int u = it*256 + tid;            // 512 float4 = 32 rows x 64 k
            int rr = u >> 4, k4 = u & 15;
            float4 v = *(const float4*)&d_A[(size_t)(n0+rr)*AGK + kb + k4*4];
            As2[(k4*4+0)*32 + rr] = make_float2(v.x,v.x);
            As2[(k4*4+1)*32 + rr] = make_float2(v.y,v.y);
            As2[(k4*4+2)*32 + rr] = make_float2(v.z,v.z);
            As2[(k4*4+3)*32 + rr] = make_float2(v.w,v.w);
        }
        #pragma unroll
        for (int it=0; it<8; it++){
            int u = it*256 + tid;            // 2048 float4 = 64 k x 128 c
            int kk = u >> 5, c4 = u & 31;
            *(float4*)&Xs[kk*128 + c4*4] =
                *(const float4*)&d_x1gT[(size_t)(kb+kk)*1024 + c0 + c4*4];
        }
        __syncthreads();

        #pragma unroll 4
        for (int k=0;k<64;k++){
            float4 bv = *(const float4*)&Xs[k*128 + tx*4];
            ull b0,b1;
            asm("mov.b64 %0,{%1,%2};" : "=l"(b0) : "f"(bv.x), "f"(bv.y));
            asm("mov.b64 %0,{%1,%2};" : "=l"(b1) : "f"(bv.z), "f"(bv.w));
            const ull* Ar = (const ull*)&As2[k*32 + ty*4];
            #pragma unroll
            for (int i=0;i<4;i++){
                ull a2 = Ar[i];
                asm("fma.rn.f32x2 %0, %1, %2, %0;" : "+l"(acc[i][0]) : "l"(a2), "l"(b0));
                asm("fma.rn.f32x2 %0, %1, %2, %0;" : "+l"(acc[i][1]) : "l"(a2), "l"(b1));
            }
        }
    }
    #pragma unroll
    for (int i=0;i<4;i++){
        int n = n0 + ty*4 + i;
        if (n < Nn){
            float4 v;
            asm("mov.b64 {%0,%1},%2;" : "=f"(v.x), "=f"(v.y) : "l"(acc[i][0]));
            asm("mov.b64 {%0,%1},%2;" : "=f"(v.z), "=f"(v.w) : "l"(acc[i][1]));
            *(float4*)&d_yT[(size_t)n*1024 + c0 + tx*4] = v;
        }
    }
}

// AGC per node, split into 2 blocks per node (half of o each).
__global__ void __launch_bounds__(128) k_x2(){
    __shared__ float sw0[64*32];
    __shared__ float sw1[64*32];
    __shared__ float sxs[1024];
    __shared__ float sys[1024];
    int n = blockIdx.x, half = blockIdx.y;
    int tid = threadIdx.x;
    const float4* Wg = (const float4*)&d_agcW[(size_t)n*8192];
    float4* s0 = (float4*)sw0;
    float4* s1 = (float4*)sw1;
    #pragma unroll
    for (int it=0; it<4; it++){
        int u = it*128 + tid;
        int i = u >> 3, c4 = u & 7;
        s0[u] = Wg[i*16 + half*8 + c4];
        s1[u] = Wg[1024 + i*16 + half*8 + c4];
    }
    #pragma unroll
    for (int it=0; it<2; it++){
        int u = it*128 + tid;
        ((float4*)sxs)[u] = ((const float4*)&d_x1gT[(size_t)n*1024])[u];
        ((float4*)sys)[u] = ((const float4*)&d_yT[(size_t)n*1024])[u];
    }
    __syncthreads();

    int o4 = tid & 7, b = tid >> 3;
    float4 bias = *(const float4*)&d_agcb[n*64 + half*32 + o4*4];
    ull acc0, acc1;
    asm("mov.b64 %0,{%1,%2};" : "=l"(acc0) : "f"(bias.x), "f"(bias.y));
    asm("mov.b64 %0,{%1,%2};" : "=l"(acc1) : "f"(bias.z), "f"(bias.w));
    const ull* W0p = (const ull*)sw0;
    const ull* W1p = (const ull*)sw1;
    const float* xr = &sxs[b*64];
    const float* yr = &sys[b*64];
    #pragma unroll 8
    for (int i=0;i<64;i++){
        ull w00 = W0p[i*16 + o4*2], w01 = W0p[i*16 + o4*2 + 1];
        ull w10 = W1p[i*16 + o4*2], w11 = W1p[i*16 + o4*2 + 1];
        float xv = xr[i], yv = yr[i];
        ull xx, yy;
        asm("mov.b64 %0,{%1,%1};" : "=l"(xx) : "f"(xv));
        asm("mov.b64 %0,{%1,%1};" : "=l"(yy) : "f"(yv));
        asm("fma.rn.f32x2 %0, %1, %2, %0;" : "+l"(acc0) : "l"(w00), "l"(xx));
        asm("fma.rn.f32x2 %0, %1, %2, %0;" : "+l"(acc1) : "l"(w01), "l"(xx));
        asm("fma.rn.f32x2 %0, %1, %2, %0;" : "+l"(acc0) : "l"(w10), "l"(yy));
        asm("fma.rn.f32x2 %0, %1, %2, %0;" : "+l"(acc1) : "l"(w11), "l"(yy));
    }
    float4 r;
    asm("mov.b64 {%0,%1},%2;" : "=f"(r.x), "=f"(r.y) : "l"(acc0));
    asm("mov.b64 {%0,%1},%2;" : "=f"(r.z), "=f"(r.w) : "l"(acc1));
    r.x = fmaxf(r.x,0.f); r.y = fmaxf(r.y,0.f);
    r.z = fmaxf(r.z,0.f); r.w = fmaxf(r.w,0.f);
    *(float4*)&d_x2[((size_t)b*Nn + n)*64 + half*32 + o4*4] = r;
}

// big fused GEMM+tanh+contract: 64x256 tile, 256 threads, 2 blocks/SM.
#define GZ_X2STRIDE 66
#define GZ_SMEM ((64*GZ_X2STRIDE*2 + 64*256 + 256)*4)   // ~100KB

__global__ void __launch_bounds__(256, 2) k_gz(
                     const float* __restrict__ gWout, const float* __restrict__ gbout,
                     int stage){
    extern __shared__ float sm[];
    float2* Xs2 = (float2*)sm;                  // [k][row dup], stride 66
    float* Ws = sm + 64*GZ_X2STRIDE*2;          // [k][256]
    float* sb = Ws + 64*256;
    int tid = threadIdx.x;
    int r0 = blockIdx.x * 64;
    int c0 = blockIdx.y * 256;

    #pragma unroll
    for (int it=0; it<4; it++){
        int u = it*256 + tid;                   // 1024 float4 = 64 rows x 16 kq
        int row = u >> 4, kq = u & 15;
        int r = r0 + row;
        float4 v = (r < Rr) ? *(const float4*)&d_x2[(size_t)r*64 + kq*4]
                            : make_float4(0.f,0.f,0.f,0.f);
        Xs2[(kq*4+0)*GZ_X2STRIDE + row] = make_float2(v.x, v.x);
        Xs2[(kq*4+1)*GZ_X2STRIDE + row] = make_float2(v.y, v.y);
        Xs2[(kq*4+2)*GZ_X2STRIDE + row] = make_float2(v.z, v.z);
        Xs2[(kq*4+3)*GZ_X2STRIDE + row] = make_float2(v.w, v.w);
    }
    #pragma unroll
    for (int it=0; it<16; it++){
        int u = it*256 + tid;                   // 4096 float4 = 64 k x 64 c4
        int k = u >> 6, c4 = u & 63;
        *(float4*)&Ws[k*256 + c4*4] = *(const float4*)&gWout[(size_t)k*4096 + c0 + c4*4];
    }
    sb[tid] = gbout[c0 + tid];
    __syncthreads();

    int tx = tid & 31, ty = tid >> 5;           // ty 0..7 -> rows ty*8..+8
    ull acc[8][4];
    #pragma unroll
    for (int i=0;i<8;i++)
        #pragma unroll
        for (int p=0;p<4;p++) acc[i][p] = 0ull;

    #pragma unroll 2
    for (int k=0;k<64;k++){
        float4 bA  = *(const float4*)&Ws[k*256 + tx*4];
        float4 bB  = *(const float4*)&Ws[k*256 + 128 + tx*4];
        ull b0,b1,b2,b3;
        asm("mov.b64 %0,{%1,%2};" : "=l"(b0) : "f"(bA.x), "f"(bA.y));
        asm("mov.b64 %0,{%1,%2};" : "=l"(b1) : "f"(bA.z), "f"(bA.w));
        asm("mov.b64 %0,{%1,%2};" : "=l"(b2) : "f"(bB.x), "f"(bB.y));
        asm("mov.b64 %0,{%1,%2};" : "=l"(b3) : "f"(bB.z), "f"(bB.w));
        const ull* Xrow = (const ull*)&Xs2[k*GZ_X2STRIDE + ty*8];
        #pragma unroll
        for (int i=0;i<8;i++){
            ull a2 = Xrow[i];
            asm("fma.rn.f32x2 %0, %1, %2, %0;" : "+l"(acc[i][0]) : "l"(a2), "l"(b0));
            asm("fma.rn.f32x2 %0, %1, %2, %0;" : "+l"(acc[i][1]) : "l"(a2), "l"(b1));
            asm("fma.rn.f32x2 %0, %1, %2, %0;" : "+l"(acc[i][2]) : "l"(a2), "l"(b2));
            asm("fma.rn.f32x2 %0, %1, %2, %0;" : "+l"(acc[i][3]) : "l"(a2), "l"(b3));
        }
    }

    float w = (stage==1 || stage==2) ? 2.f : 1.f;
    int jb = (4*tx) & 63;
    float bA0 = sb[4*tx],       bA1 = sb[4*tx+1];
    float bA2 = sb[4*tx+2],     bA3 = sb[4*tx+3];
    float bB0 = sb[128+4*tx],   bB1 = sb[128+4*tx+1];
    float bB2 = sb[128+4*tx+2], bB3 = sb[128+4*tx+3];
    float sA[8], sB[8];
    #pragma unroll
    for (int i=0;i<8;i++){
        int r = r0 + ty*8 + i;
        float4 dhv = make_float4(0.f,0.f,0.f,0.f);
        if (r < Rr) dhv = *(const float4*)&d_kh[(size_t)r*64 + jb];
        float g0,g1;
        asm("mov.b64 {%0,%1},%2;" : "=f"(g0), "=f"(g1) : "l"(acc[i][0]));
        float s = fast_tanh(g0+bA0)*dhv.x + fast_tanh(g1+bA1)*dhv.y;
        asm("mov.b64 {%0,%1},%2;" : "=f"(g0), "=f"(g1) : "l"(acc[i][1]));
        s += fast_tanh(g0+bA2)*dhv.z + fast_tanh(g1+bA3)*dhv.w;
        sA[i] = s;
        asm("mov.b64 {%0,%1},%2;" : "=f"(g0), "=f"(g1) : "l"(acc[i][2]));
        s = fast_tanh(g0+bB0)*dhv.x + fast_tanh(g1+bB1)*dhv.y;
        asm("mov.b64 {%0,%1},%2;" : "=f"(g0), "=f"(g1) : "l"(acc[i][3]));
        s += fast_tanh(g0+bB2)*dhv.z + fast_tanh(g1+bB3)*dhv.w;
        sB[i] = s;
    }
    #pragma unroll
    for (int s2=1; s2<16; s2<<=1){
        #pragma unroll
        for (int i=0;i<8;i++){
            sA[i] += __shfl_xor_sync(0xffffffffu, sA[i], s2);
            sB[i] += __shfl_xor_sync(0xffffffffu, sB[i], s2);
        }
    }
    if (tx == 0 || tx == 16){
        int ihalf = (tx == 16) ? 1 : 0;
        int iA = blockIdx.y*4 + ihalf;
        int iB = iA + 2;
        #pragma unroll
        for (int i=0;i<8;i++){
            int r = r0 + ty*8 + i;
            if (r < Rr){
                size_t oA = (size_t)r*64 + iA;
                size_t oB = (size_t)r*64 + iB;
                d_kz[oA] = sA[i];
                d_kz[oB] = sB[i];
                d_accz[oA] = (stage==0) ? sA[i] : (d_accz[oA] + w*sA[i]);
                d_accz[oB] = (stage==0) ? sB[i] : (d_accz[oB] + w*sB[i]);
            }
        }
    }
}

// output conv; applies the final RK4 update to z
__global__ void k_out(const float* __restrict__ convW, const float* __restrict__ convb,
                      const float* __restrict__ times, float* __restrict__ out){
    __shared__ float szr[64];
    int r = blockIdx.x, t = threadIdx.x;
    float sc = (times[NSTEP] - times[NSTEP-1]) * (1.f/6.f);
    size_t base = (size_t)r*64 + t;
    szr[t] = d_z[base] + sc*d_accz[base];
    __syncthreads();
    if (t < 12){
        float acc = convb[t];
        #pragma unroll 8
        for (int h=0; h<64; h++) acc = fmaf(szr[h], convW[t*64+h], acc);
        int b = r / Nn, n = r - b*Nn;
        out[(size_t)(b*12 + t)*Nn + n] = acc;
    }
}

// ---------------- launcher ----------------
extern "C" void kernel_launch(void* const* d_in, const int* in_sizes, int n_in,
                              void* d_out, int out_size){
    const float* coeff_a = (const float*)d_in[0];
    const float* coeff_b = (const float*)d_in[1];
    const float* coeff_c = (const float*)d_in[2];
    const float* coeff_d = (const float*)d_in[3];
    const float* times   = (const float*)d_in[4];
    const float* h_W     = (const float*)d_in[5];
    const float* h_b     = (const float*)d_in[6];
    const float* z_W     = (const float*)d_in[7];
    const float* z_b     = (const float*)d_in[8];
    const float* f_W_in  = (const float*)d_in[9];
    const float* f_b_in  = (const float*)d_in[10];
    const float* f_W_mid = (const float*)d_in[11];
    const float* f_b_mid = (const float*)d_in[12];
    const float* f_W_out = (const float*)d_in[13];
    const float* f_b_out = (const float*)d_in[14];
    const float* g_W_in  = (const float*)d_in[15];
    const float* g_b_in  = (const float*)d_in[16];
    const float* g_E     = (const float*)d_in[17];
    const float* g_Wpool = (const float*)d_in[18];
    const float* g_bpool = (const float*)d_in[19];
    const float* g_W_out = (const float*)d_in[20];
    const float* g_b_out = (const float*)d_in[21];
    const float* conv_W  = (const float*)d_in[22];
    const float* conv_b  = (const float*)d_in[23];
    float* out = (float*)d_out;

    cudaFuncSetAttribute(k_agg, cudaFuncAttributeMaxDynamicSharedMemorySize, AGG_SMEM);
    cudaFuncSetAttribute(k_gz,  cudaFuncAttributeMaxDynamicSharedMemorySize, GZ_SMEM);

    for (int step = 0; step < NSTEP; step++){
        for (int stage = 0; stage < 4; stage++){
            int grid = (step==0 && stage==0) ? FG1_GRID_PRE : FG1_BLKS;
            k_fg1<<<grid, 64>>>(times, coeff_a, coeff_b, coeff_c, coeff_d,
                                h_W, h_b, z_W, z_b,
                                f_W_in, f_b_in, f_W_mid, f_b_mid, f_W_out, f_b_out,
                                g_W_in, g_b_in, g_E, g_bpool, g_Wpool, step, stage);
            k_agg<<<dim3(10,8), 256, AGG_SMEM>>>();
            k_x2<<<dim3(Nn,2), 128>>>();
            k_gz<<<dim3(77,16), 256, GZ_SMEM>>>(g_W_out, g_b_out, stage);
        }
    }
    k_out<<<Rr, 64>>>(conv_W, conv_b, times, out);
}